// round 1
// baseline (speedup 1.0000x reference)
#include <cuda_runtime.h>
#include <cstddef>

// Problem constants (fixed by the reference: B=4, S=2048, D=1024)
#define BB 4
#define SS 2048
#define DD 1024

// Scratch: Q, K, V projections (32 MB each) and score matrix (64 MB).
// __device__ globals per the no-allocation rule.
__device__ float g_q[(size_t)BB * SS * DD];
__device__ float g_k[(size_t)BB * SS * DD];
__device__ float g_v[(size_t)BB * SS * DD];
__device__ float g_s[(size_t)BB * SS * SS];

// ---------------------------------------------------------------------------
// Tiled SGEMM: C = alpha * A * op(B) (+ bias), batched via blockIdx.z strides.
//   A: [M,K] row-major
//   B: !TRANS_B -> [K,N] row-major ; TRANS_B -> [N,K] row-major (computes A*B^T)
// Tile: 128x128x8, 256 threads, 8x8 per-thread microtile.
// Requires M%128==0, N%128==0, K%8==0 (true for all uses here).
// ---------------------------------------------------------------------------
#define BM 128
#define BN 128
#define BK 8
#define TM 8
#define TN 8

template<bool TRANS_B, bool ADD_BIAS>
__global__ __launch_bounds__(256, 2) void sgemm_kernel(
    const float* __restrict__ A, const float* __restrict__ Bm,
    const float* __restrict__ bias, float* __restrict__ C,
    int M, int N, int K, float alpha,
    size_t strideA, size_t strideB, size_t strideC)
{
    A  += (size_t)blockIdx.z * strideA;
    Bm += (size_t)blockIdx.z * strideB;
    C  += (size_t)blockIdx.z * strideC;

    __shared__ float As[BK][BM];
    __shared__ float Bs[BK][BN];

    const int tid = threadIdx.x;
    const int bm = blockIdx.y * BM;
    const int bn = blockIdx.x * BN;
    const int ty = tid >> 4;      // 0..15
    const int tx = tid & 15;      // 0..15

    // A tile load mapping: 128 rows x 8 cols = 256 float4
    const int a_row = tid >> 1;            // 0..127
    const int a_col = (tid & 1) << 2;      // 0 or 4
    // B tile load mapping
    const int bt_row = tid >> 1;           // TRANS_B: 0..127 (N dim)
    const int bt_col = (tid & 1) << 2;
    const int bn_row = tid >> 5;           // !TRANS_B: 0..7 (K dim)
    const int bn_col = (tid & 31) << 2;    // 0..124

    const float* Aptr = A + (size_t)(bm + a_row) * K + a_col;
    const float* Bptr = TRANS_B
        ? Bm + (size_t)(bn + bt_row) * K + bt_col
        : Bm + (size_t)bn_row * N + bn + bn_col;

    float acc[TM][TN];
    #pragma unroll
    for (int i = 0; i < TM; i++)
        #pragma unroll
        for (int j = 0; j < TN; j++)
            acc[i][j] = 0.0f;

    for (int k0 = 0; k0 < K; k0 += BK) {
        float4 av = *reinterpret_cast<const float4*>(Aptr + k0);
        As[a_col + 0][a_row] = av.x;
        As[a_col + 1][a_row] = av.y;
        As[a_col + 2][a_row] = av.z;
        As[a_col + 3][a_row] = av.w;

        if (TRANS_B) {
            float4 bv = *reinterpret_cast<const float4*>(Bptr + k0);
            Bs[bt_col + 0][bt_row] = bv.x;
            Bs[bt_col + 1][bt_row] = bv.y;
            Bs[bt_col + 2][bt_row] = bv.z;
            Bs[bt_col + 3][bt_row] = bv.w;
        } else {
            float4 bv = *reinterpret_cast<const float4*>(Bptr + (size_t)k0 * N);
            *reinterpret_cast<float4*>(&Bs[bn_row][bn_col]) = bv;
        }
        __syncthreads();

        #pragma unroll
        for (int kk = 0; kk < BK; kk++) {
            float ar[TM], br[TN];
            #pragma unroll
            for (int i = 0; i < TM; i++) ar[i] = As[kk][ty * TM + i];
            #pragma unroll
            for (int j = 0; j < TN; j++) br[j] = Bs[kk][tx * TN + j];
            #pragma unroll
            for (int i = 0; i < TM; i++)
                #pragma unroll
                for (int j = 0; j < TN; j++)
                    acc[i][j] = fmaf(ar[i], br[j], acc[i][j]);
        }
        __syncthreads();
    }

    #pragma unroll
    for (int i = 0; i < TM; i++) {
        float* crow = C + (size_t)(bm + ty * TM + i) * N + bn + tx * TN;
        #pragma unroll
        for (int j = 0; j < TN; j += 4) {
            float4 cv;
            cv.x = acc[i][j + 0] * alpha;
            cv.y = acc[i][j + 1] * alpha;
            cv.z = acc[i][j + 2] * alpha;
            cv.w = acc[i][j + 3] * alpha;
            if (ADD_BIAS) {
                const int c0 = bn + tx * TN + j;
                cv.x += bias[c0 + 0];
                cv.y += bias[c0 + 1];
                cv.z += bias[c0 + 2];
                cv.w += bias[c0 + 3];
            }
            *reinterpret_cast<float4*>(crow + j) = cv;
        }
    }
}

// ---------------------------------------------------------------------------
// Row softmax over the score matrix (in place). One block per row of length SS.
// ---------------------------------------------------------------------------
__global__ __launch_bounds__(256) void softmax_kernel(float* __restrict__ s)
{
    __shared__ float red[256];
    float* row = s + (size_t)blockIdx.x * SS;
    const int tid = threadIdx.x;

    float m = -3.4e38f;
    #pragma unroll 2
    for (int i = tid; i < SS; i += 256) m = fmaxf(m, row[i]);
    red[tid] = m;
    __syncthreads();
    #pragma unroll
    for (int o = 128; o > 0; o >>= 1) {
        if (tid < o) red[tid] = fmaxf(red[tid], red[tid + o]);
        __syncthreads();
    }
    m = red[0];
    __syncthreads();

    float sum = 0.0f;
    #pragma unroll 2
    for (int i = tid; i < SS; i += 256) {
        float e = __expf(row[i] - m);
        row[i] = e;
        sum += e;
    }
    red[tid] = sum;
    __syncthreads();
    #pragma unroll
    for (int o = 128; o > 0; o >>= 1) {
        if (tid < o) red[tid] += red[tid + o];
        __syncthreads();
    }
    const float inv = 1.0f / red[0];
    __syncthreads();

    #pragma unroll 2
    for (int i = tid; i < SS; i += 256) row[i] *= inv;
}

// ---------------------------------------------------------------------------
// kernel_launch: x, Wk, bk, Wq, bq, Wv, bv, dims
// ---------------------------------------------------------------------------
extern "C" void kernel_launch(void* const* d_in, const int* in_sizes, int n_in,
                              void* d_out, int out_size)
{
    const float* x  = (const float*)d_in[0];
    const float* Wk = (const float*)d_in[1];
    const float* bk = (const float*)d_in[2];
    const float* Wq = (const float*)d_in[3];
    const float* bq = (const float*)d_in[4];
    const float* Wv = (const float*)d_in[5];
    const float* bv = (const float*)d_in[6];
    float* out = (float*)d_out;

    float *qp, *kp, *vp, *sp;
    cudaGetSymbolAddress((void**)&qp, g_q);
    cudaGetSymbolAddress((void**)&kp, g_k);
    cudaGetSymbolAddress((void**)&vp, g_v);
    cudaGetSymbolAddress((void**)&sp, g_s);

    const int M = BB * SS;   // 8192 flattened rows for projections
    dim3 block(256);

    // 1) Projections: [8192,1024] x [1024,1024] + bias
    {
        dim3 grid(DD / BN, M / BM, 1);
        sgemm_kernel<false, true><<<grid, block>>>(x, Wk, bk, kp, M, DD, DD, 1.0f, 0, 0, 0);
        sgemm_kernel<false, true><<<grid, block>>>(x, Wq, bq, qp, M, DD, DD, 1.0f, 0, 0, 0);
        sgemm_kernel<false, true><<<grid, block>>>(x, Wv, bv, vp, M, DD, DD, 1.0f, 0, 0, 0);
    }

    // 2) Scores: per batch, S = Q * K^T / sqrt(D)
    {
        dim3 grid(SS / BN, SS / BM, BB);
        const float alpha = 1.0f / 32.0f;  // 1/sqrt(1024)
        sgemm_kernel<true, false><<<grid, block>>>(
            qp, kp, nullptr, sp, SS, SS, DD, alpha,
            (size_t)SS * DD, (size_t)SS * DD, (size_t)SS * SS);
    }

    // 3) Row softmax over keys (axis=2)
    softmax_kernel<<<BB * SS, 256>>>(sp);

    // 4) AV: per batch, O = P * V
    {
        dim3 grid(DD / BN, SS / BM, BB);
        sgemm_kernel<false, false><<<grid, block>>>(
            sp, vp, nullptr, out, SS, DD, SS, 1.0f,
            (size_t)SS * SS, (size_t)SS * DD, (size_t)SS * DD);
    }
}

// round 3
// speedup vs baseline: 1.5215x; 1.5215x over previous
#include <cuda_runtime.h>
#include <cuda_bf16.h>
#include <cstdint>
#include <cstddef>

// Problem constants (B=4, S=2048, D=1024)
#define BB 4
#define SS 2048
#define DD 1024

// Scratch (__device__ globals per no-allocation rule)
__device__ float g_q [(size_t)BB * SS * DD];       // Q  [B*S, D]
__device__ float g_k [(size_t)BB * SS * DD];       // K  [B*S, D]
__device__ float g_vt[(size_t)BB * DD * SS];       // V^T per batch [D, S]
__device__ float g_s [(size_t)BB * SS * SS];       // scores / probs
__device__ float g_wt[3][(size_t)DD * DD];         // Wk^T, Wq^T, Wv^T

// ============================ helpers ============================
__device__ __forceinline__ uint32_t smem_u32(const void* p) {
    uint32_t a;
    asm("{ .reg .u64 t; cvta.to.shared.u64 t, %1; cvt.u32.u64 %0, t; }"
        : "=r"(a) : "l"(p));
    return a;
}

// 128B-row XOR swizzle: 16B-chunk index (bits 4-6) ^= row-within-8 (bits 7-9)
#define SWZ(off) ((uint32_t)(off) ^ ((((uint32_t)(off)) >> 3) & 0x70u))

__device__ __forceinline__ void ldsm_x4(uint32_t* r, uint32_t addr) {
    asm volatile("ldmatrix.sync.aligned.m8n8.x4.shared.b16 {%0,%1,%2,%3}, [%4];"
                 : "=r"(r[0]), "=r"(r[1]), "=r"(r[2]), "=r"(r[3]) : "r"(addr));
}

__device__ __forceinline__ void mma16816(float* c, const uint32_t* a,
                                         uint32_t b0, uint32_t b1) {
    asm volatile(
        "mma.sync.aligned.m16n8k16.row.col.f32.bf16.bf16.f32 "
        "{%0,%1,%2,%3}, {%4,%5,%6,%7}, {%8,%9}, {%0,%1,%2,%3};"
        : "+f"(c[0]), "+f"(c[1]), "+f"(c[2]), "+f"(c[3])
        : "r"(a[0]), "r"(a[1]), "r"(a[2]), "r"(a[3]), "r"(b0), "r"(b1));
}

__device__ __forceinline__ void cvt_split(float4 v, uint2& hi, uint2& lo) {
    __nv_bfloat162 h0 = __floats2bfloat162_rn(v.x, v.y);
    __nv_bfloat162 h1 = __floats2bfloat162_rn(v.z, v.w);
    float lx = v.x - __bfloat162float(h0.x);
    float ly = v.y - __bfloat162float(h0.y);
    float lz = v.z - __bfloat162float(h1.x);
    float lw = v.w - __bfloat162float(h1.y);
    __nv_bfloat162 l0 = __floats2bfloat162_rn(lx, ly);
    __nv_bfloat162 l1 = __floats2bfloat162_rn(lz, lw);
    hi.x = *reinterpret_cast<uint32_t*>(&h0);
    hi.y = *reinterpret_cast<uint32_t*>(&h1);
    lo.x = *reinterpret_cast<uint32_t*>(&l0);
    lo.y = *reinterpret_cast<uint32_t*>(&l1);
}

// ============================ GEMM kernel ============================
// D = alpha * A[M,K] * B[N,K]^T (+ bias), fp32 in/out, 3x bf16-split on HMMA.
// Block 128x128, 8 warps (2x4 of 64x32), K chunk = 32 fp32.
// smem stage: A region 16KB (128 rows x 128B = [hi32|lo32] bf16), B region 16KB.
// Double buffered: 2 x 32KB = 64KB dynamic smem.
#define CK 32
#define STAGE_BYTES 32768
#define B_REGION   16384
#define GEMM_SMEM  (2 * STAGE_BYTES)

template<bool HAS_BIAS, bool BIAS_ROW>
__global__ __launch_bounds__(256) void mma_gemm(
    const float* __restrict__ A, const float* __restrict__ B,
    const float* __restrict__ bias, float* __restrict__ C,
    int M, int N, int K, float alpha,
    long sA, long sB, long sC)
{
    extern __shared__ __align__(1024) char smem[];
    const uint32_t sbase = smem_u32(smem);

    A += (size_t)blockIdx.z * sA;
    B += (size_t)blockIdx.z * sB;
    C += (size_t)blockIdx.z * sC;

    const int tid  = threadIdx.x;
    const int w    = tid >> 5;
    const int lane = tid & 31;
    const int bm = blockIdx.y * 128;
    const int bn = blockIdx.x * 128;
    const int wm = (w & 1) * 64;       // warp M offset (2 rows of warps)
    const int wn = (w >> 1) * 32;      // warp N offset (4 cols of warps)

    // ---- load mapping: warp w owns rows [w*16, w*16+16) ----
    const int kq   = lane & 7;                                   // float4 col
    const int rsel = ((lane >> 3) & 1) * 4 + ((lane >> 4) & 1) * 2; // 0,4,2,6
    const int r0   = w * 16 + rsel;
    const int dj[4] = {0, 1, 8, 9};

    const float* Ag = A + (size_t)(bm + r0) * K + kq * 4;
    const float* Bg = B + (size_t)(bn + r0) * K + kq * 4;
    size_t djK[4];
    uint32_t offH[4], offL[4];
    #pragma unroll
    for (int j = 0; j < 4; j++) {
        djK[j]  = (size_t)dj[j] * K;
        offH[j] = SWZ((r0 + dj[j]) * 128 + kq * 8);
        offL[j] = SWZ((r0 + dj[j]) * 128 + 64 + kq * 8);
    }

    float acc[4][4][4];
    #pragma unroll
    for (int mi = 0; mi < 4; mi++)
        #pragma unroll
        for (int ni = 0; ni < 4; ni++)
            #pragma unroll
            for (int q = 0; q < 4; q++)
                acc[mi][ni][q] = 0.0f;

    const int nk = K / CK;

    // ---- prologue: chunk 0 into buffer 0 ----
    {
        #pragma unroll
        for (int j = 0; j < 4; j++) {
            uint2 h, l;
            float4 va = *reinterpret_cast<const float4*>(Ag + djK[j]);
            cvt_split(va, h, l);
            *reinterpret_cast<uint2*>(smem + offH[j]) = h;
            *reinterpret_cast<uint2*>(smem + offL[j]) = l;
            float4 vb = *reinterpret_cast<const float4*>(Bg + djK[j]);
            cvt_split(vb, h, l);
            *reinterpret_cast<uint2*>(smem + B_REGION + offH[j]) = h;
            *reinterpret_cast<uint2*>(smem + B_REGION + offL[j]) = l;
        }
    }
    __syncthreads();

    const int arow = lane & 15;
    const int acol16 = lane & 16;   // 0 or 16 byte col offset within frag

    for (int c = 0; c < nk; c++) {
        const int s = c & 1;

        // stage next chunk's globals in registers (hidden under mma)
        float4 va[4], vb[4];
        if (c + 1 < nk) {
            const float* ap = Ag + (size_t)(c + 1) * CK;
            const float* bp = Bg + (size_t)(c + 1) * CK;
            #pragma unroll
            for (int j = 0; j < 4; j++) {
                va[j] = *reinterpret_cast<const float4*>(ap + djK[j]);
                vb[j] = *reinterpret_cast<const float4*>(bp + djK[j]);
            }
        }

        // ---- mma over buffer s ----
        const uint32_t saA = sbase + s * STAGE_BYTES;
        const uint32_t saB = saA + B_REGION;
        #pragma unroll
        for (int ks = 0; ks < 2; ks++) {
            const int cbH = ks * 32 + acol16;
            const int cbL = cbH + 64;
            uint32_t ra[4][4], rbh[2][4], rbl[2][4];
            #pragma unroll
            for (int mi = 0; mi < 4; mi++)
                ldsm_x4(ra[mi], saA + SWZ((wm + mi * 16 + arow) * 128 + cbH));
            #pragma unroll
            for (int ng = 0; ng < 2; ng++) {
                ldsm_x4(rbh[ng], saB + SWZ((wn + ng * 16 + arow) * 128 + cbH));
                ldsm_x4(rbl[ng], saB + SWZ((wn + ng * 16 + arow) * 128 + cbL));
            }
            // Ah*Bh and Ah*Bl
            #pragma unroll
            for (int mi = 0; mi < 4; mi++)
                #pragma unroll
                for (int ni = 0; ni < 4; ni++) {
                    mma16816(acc[mi][ni], ra[mi],
                             rbh[ni >> 1][ni & 1], rbh[ni >> 1][2 + (ni & 1)]);
                    mma16816(acc[mi][ni], ra[mi],
                             rbl[ni >> 1][ni & 1], rbl[ni >> 1][2 + (ni & 1)]);
                }
            // Al*Bh
            #pragma unroll
            for (int mi = 0; mi < 4; mi++)
                ldsm_x4(ra[mi], saA + SWZ((wm + mi * 16 + arow) * 128 + cbL));
            #pragma unroll
            for (int mi = 0; mi < 4; mi++)
                #pragma unroll
                for (int ni = 0; ni < 4; ni++)
                    mma16816(acc[mi][ni], ra[mi],
                             rbh[ni >> 1][ni & 1], rbh[ni >> 1][2 + (ni & 1)]);
        }
        __syncthreads();  // all warps done reading buf s / free to overwrite s^1

        if (c + 1 < nk) {
            char* dst = smem + ((c + 1) & 1) * STAGE_BYTES;
            #pragma unroll
            for (int j = 0; j < 4; j++) {
                uint2 h, l;
                cvt_split(va[j], h, l);
                *reinterpret_cast<uint2*>(dst + offH[j]) = h;
                *reinterpret_cast<uint2*>(dst + offL[j]) = l;
                cvt_split(vb[j], h, l);
                *reinterpret_cast<uint2*>(dst + B_REGION + offH[j]) = h;
                *reinterpret_cast<uint2*>(dst + B_REGION + offL[j]) = l;
            }
            __syncthreads();
        }
    }

    // ---- epilogue ----
    const int g = lane >> 2;
    const int t = lane & 3;
    #pragma unroll
    for (int mi = 0; mi < 4; mi++) {
        #pragma unroll
        for (int half = 0; half < 2; half++) {
            const int row = bm + wm + mi * 16 + g + half * 8;
            float br = 0.0f;
            if (HAS_BIAS && BIAS_ROW) br = bias[row];
            float* cp = C + (size_t)row * N + bn + wn;
            #pragma unroll
            for (int ni = 0; ni < 4; ni++) {
                float2 v;
                v.x = acc[mi][ni][half * 2 + 0] * alpha;
                v.y = acc[mi][ni][half * 2 + 1] * alpha;
                if (HAS_BIAS) {
                    if (BIAS_ROW) { v.x += br; v.y += br; }
                    else {
                        const int cc = bn + wn + ni * 8 + t * 2;
                        v.x += bias[cc];
                        v.y += bias[cc + 1];
                    }
                }
                *reinterpret_cast<float2*>(cp + ni * 8 + t * 2) = v;
            }
        }
    }
}

// ============================ transpose (1024x1024) ============================
__global__ __launch_bounds__(256) void transpose_k(
    const float* __restrict__ in, float* __restrict__ out)
{
    __shared__ float t[32][33];
    const int tx = threadIdx.x, ty = threadIdx.y;
    const int x = blockIdx.x * 32 + tx;
    const int y0 = blockIdx.y * 32;
    #pragma unroll
    for (int i = ty; i < 32; i += 8)
        t[i][tx] = in[(size_t)(y0 + i) * DD + x];
    __syncthreads();
    const int xo = blockIdx.y * 32 + tx;
    const int yo = blockIdx.x * 32;
    #pragma unroll
    for (int i = ty; i < 32; i += 8)
        out[(size_t)(yo + i) * DD + xo] = t[tx][i];
}

// ============================ softmax ============================
__global__ __launch_bounds__(256) void softmax_kernel(float* __restrict__ s)
{
    __shared__ float red[256];
    float* row = s + (size_t)blockIdx.x * SS;
    const int tid = threadIdx.x;

    float m = -3.4e38f;
    #pragma unroll 2
    for (int i = tid; i < SS; i += 256) m = fmaxf(m, row[i]);
    red[tid] = m;
    __syncthreads();
    #pragma unroll
    for (int o = 128; o > 0; o >>= 1) {
        if (tid < o) red[tid] = fmaxf(red[tid], red[tid + o]);
        __syncthreads();
    }
    m = red[0];
    __syncthreads();

    float sum = 0.0f;
    #pragma unroll 2
    for (int i = tid; i < SS; i += 256) {
        float e = __expf(row[i] - m);
        row[i] = e;
        sum += e;
    }
    red[tid] = sum;
    __syncthreads();
    #pragma unroll
    for (int o = 128; o > 0; o >>= 1) {
        if (tid < o) red[tid] += red[tid + o];
        __syncthreads();
    }
    const float inv = 1.0f / red[0];
    __syncthreads();

    #pragma unroll 2
    for (int i = tid; i < SS; i += 256) row[i] *= inv;
}

// ============================ launch ============================
extern "C" void kernel_launch(void* const* d_in, const int* in_sizes, int n_in,
                              void* d_out, int out_size)
{
    const float* x  = (const float*)d_in[0];
    const float* Wk = (const float*)d_in[1];
    const float* bk = (const float*)d_in[2];
    const float* Wq = (const float*)d_in[3];
    const float* bq = (const float*)d_in[4];
    const float* Wv = (const float*)d_in[5];
    const float* bv = (const float*)d_in[6];
    float* out = (float*)d_out;

    float *qp, *kp, *vtp, *sp, *wtp;
    cudaGetSymbolAddress((void**)&qp,  g_q);
    cudaGetSymbolAddress((void**)&kp,  g_k);
    cudaGetSymbolAddress((void**)&vtp, g_vt);
    cudaGetSymbolAddress((void**)&sp,  g_s);
    cudaGetSymbolAddress((void**)&wtp, g_wt);
    float* wkt = wtp;
    float* wqt = wtp + (size_t)DD * DD;
    float* wvt = wtp + 2 * (size_t)DD * DD;

    cudaFuncSetAttribute(mma_gemm<false, false>,
        cudaFuncAttributeMaxDynamicSharedMemorySize, GEMM_SMEM);
    cudaFuncSetAttribute(mma_gemm<true, false>,
        cudaFuncAttributeMaxDynamicSharedMemorySize, GEMM_SMEM);
    cudaFuncSetAttribute(mma_gemm<true, true>,
        cudaFuncAttributeMaxDynamicSharedMemorySize, GEMM_SMEM);

    dim3 tb(32, 8);
    dim3 tg(32, 32);
    transpose_k<<<tg, tb>>>(Wk, wkt);
    transpose_k<<<tg, tb>>>(Wq, wqt);
    transpose_k<<<tg, tb>>>(Wv, wvt);

    const int M = BB * SS;  // 8192
    dim3 blk(256);

    // Q = X*Wq + bq ; K = X*Wk + bk : A=X [8192,1024], B=W^T [1024,1024]
    {
        dim3 grid(DD / 128, M / 128, 1);
        mma_gemm<true, false><<<grid, blk, GEMM_SMEM>>>(
            x, wqt, bq, qp, M, DD, DD, 1.0f, 0, 0, 0);
        mma_gemm<true, false><<<grid, blk, GEMM_SMEM>>>(
            x, wkt, bk, kp, M, DD, DD, 1.0f, 0, 0, 0);
    }

    // V^T per batch: Vt[d][s] = sum_k Wv[k][d] X[s][k] + bv[d] (row bias)
    {
        dim3 grid(SS / 128, DD / 128, BB);
        mma_gemm<true, true><<<grid, blk, GEMM_SMEM>>>(
            wvt, x, bv, vtp, DD, SS, DD, 1.0f,
            0, (long)SS * DD, (long)DD * SS);
    }

    // Scores: S_b = Q_b * K_b^T / 32
    {
        dim3 grid(SS / 128, SS / 128, BB);
        mma_gemm<false, false><<<grid, blk, GEMM_SMEM>>>(
            qp, kp, nullptr, sp, SS, SS, DD, 1.0f / 32.0f,
            (long)SS * DD, (long)SS * DD, (long)SS * SS);
    }

    // Softmax over keys axis
    softmax_kernel<<<BB * SS, 256>>>(sp);

    // Out: O_b = P_b * V_b : A = P_b [2048,2048], B = Vt_b [1024,2048]
    {
        dim3 grid(DD / 128, SS / 128, BB);
        mma_gemm<false, false><<<grid, blk, GEMM_SMEM>>>(
            sp, vtp, nullptr, out, SS, DD, SS, 1.0f,
            (long)SS * SS, (long)DD * SS, (long)SS * DD);
    }
}

// round 4
// speedup vs baseline: 2.6901x; 1.7681x over previous
#include <cuda_runtime.h>
#include <cuda_bf16.h>
#include <cstdint>
#include <cstddef>

// Problem constants (B=4, S=2048, D=1024)
#define BB 4
#define SS 2048
#define DD 1024

typedef __nv_bfloat16 bf16;

// ---------------- scratch (__device__ globals, no-alloc rule) ----------------
__device__ bf16  g_xh [(size_t)BB * SS * DD];   // X hi/lo  [B*S, D]
__device__ bf16  g_xl [(size_t)BB * SS * DD];
__device__ bf16  g_wth[3][(size_t)DD * DD];     // W^T hi/lo (k,q,v)
__device__ bf16  g_wtl[3][(size_t)DD * DD];
__device__ bf16  g_qh [(size_t)BB * SS * DD];   // Q hi/lo
__device__ bf16  g_ql [(size_t)BB * SS * DD];
__device__ bf16  g_kh [(size_t)BB * SS * DD];   // K hi/lo
__device__ bf16  g_kl [(size_t)BB * SS * DD];
__device__ bf16  g_vth[(size_t)BB * DD * SS];   // V^T hi/lo [D, S] per batch
__device__ bf16  g_vtl[(size_t)BB * DD * SS];
__device__ float g_s  [(size_t)BB * SS * SS];   // scores (fp32, softmax input)
__device__ bf16  g_ph [(size_t)BB * SS * SS];   // probs hi/lo
__device__ bf16  g_pl [(size_t)BB * SS * SS];

// ---------------- helpers ----------------
__device__ __forceinline__ uint32_t smem_u32(const void* p) {
    uint32_t a;
    asm("{ .reg .u64 t; cvta.to.shared.u64 t, %1; cvt.u32.u64 %0, t; }"
        : "=r"(a) : "l"(p));
    return a;
}

// 128B-row XOR swizzle: byte bits [6:4] ^= bits [9:7]
#define SWZ(off) ((uint32_t)(off) ^ ((((uint32_t)(off)) >> 3) & 0x70u))

__device__ __forceinline__ void cp16(uint32_t dst, const void* src) {
    asm volatile("cp.async.cg.shared.global [%0], [%1], 16;"
                 :: "r"(dst), "l"(src) : "memory");
}
#define CP_COMMIT() asm volatile("cp.async.commit_group;" ::: "memory")
#define CP_WAIT(n)  asm volatile("cp.async.wait_group %0;" :: "n"(n) : "memory")

__device__ __forceinline__ void ldsm_x4(uint32_t* r, uint32_t addr) {
    asm volatile("ldmatrix.sync.aligned.m8n8.x4.shared.b16 {%0,%1,%2,%3}, [%4];"
                 : "=r"(r[0]), "=r"(r[1]), "=r"(r[2]), "=r"(r[3]) : "r"(addr));
}

__device__ __forceinline__ void mma16816(float* c, const uint32_t* a,
                                         uint32_t b0, uint32_t b1) {
    asm volatile(
        "mma.sync.aligned.m16n8k16.row.col.f32.bf16.bf16.f32 "
        "{%0,%1,%2,%3}, {%4,%5,%6,%7}, {%8,%9}, {%0,%1,%2,%3};"
        : "+f"(c[0]), "+f"(c[1]), "+f"(c[2]), "+f"(c[3])
        : "r"(a[0]), "r"(a[1]), "r"(a[2]), "r"(a[3]), "r"(b0), "r"(b1));
}

__device__ __forceinline__ void split2(float x, float y, bf16& hx, bf16& hy,
                                       bf16& lx, bf16& ly) {
    hx = __float2bfloat16(x);
    hy = __float2bfloat16(y);
    lx = __float2bfloat16(x - __bfloat162float(hx));
    ly = __float2bfloat16(y - __bfloat162float(hy));
}

// ============================ GEMM kernel ============================
// D = alpha * A[M,K] * B[N,K]^T (+bias); A,B pre-split bf16 hi/lo, K-major.
// Block 128x128, 8 warps (2x4 of 64x32), K chunk = 64 bf16, 3-stage cp.async.
// smem/stage: Ahi|Alo|Bhi|Blo, 16KB each (128 rows x 128B, swizzled) = 64KB.
#define NSTAGE 3
#define REGION 16384
#define STAGE_BYTES 65536
#define GEMM_SMEM (NSTAGE * STAGE_BYTES)

// BIAS: 0 none, 1 column (bias[col]), 2 row (bias[row])
template<int OUT_SPLIT, int BIAS>
__global__ __launch_bounds__(256) void mma_gemm(
    const bf16* __restrict__ Ahi, const bf16* __restrict__ Alo,
    const bf16* __restrict__ Bhi, const bf16* __restrict__ Blo,
    const float* __restrict__ bias,
    float* __restrict__ C, bf16* __restrict__ Chi, bf16* __restrict__ Clo,
    int M, int N, int K, float alpha,
    long sA, long sB, long sC)
{
    extern __shared__ __align__(1024) char smem[];
    const uint32_t sbase = smem_u32(smem);

    const size_t zA = (size_t)blockIdx.z * sA;
    const size_t zB = (size_t)blockIdx.z * sB;
    const size_t zC = (size_t)blockIdx.z * sC;

    const int tid  = threadIdx.x;
    const int w    = tid >> 5;
    const int lane = tid & 31;
    const int bm = blockIdx.y * 128;
    const int bn = blockIdx.x * 128;
    const int wm = (w & 1) * 64;
    const int wn = (w >> 1) * 32;

    // ---- cp.async load mapping: 256 thr x 4 passes x 16B per region ----
    const int ldr = tid >> 3;     // 0..31
    const int ldc = tid & 7;      // 16B chunk in row
    const bf16* pAh = Ahi + zA + (size_t)(bm + ldr) * K + ldc * 8;
    const bf16* pAl = Alo + zA + (size_t)(bm + ldr) * K + ldc * 8;
    const bf16* pBh = Bhi + zB + (size_t)(bn + ldr) * K + ldc * 8;
    const bf16* pBl = Blo + zB + (size_t)(bn + ldr) * K + ldc * 8;
    uint32_t soff[4];
    size_t rK[4];
    #pragma unroll
    for (int p = 0; p < 4; p++) {
        soff[p] = SWZ((ldr + p * 32) * 128 + ldc * 16);
        rK[p] = (size_t)(p * 32) * K;
    }

#define LOAD_STAGE(sbuf, k0) do {                                         \
        const uint32_t _sb = sbase + (sbuf) * STAGE_BYTES;                \
        _Pragma("unroll")                                                 \
        for (int p = 0; p < 4; p++) {                                     \
            const size_t g = rK[p] + (size_t)(k0);                        \
            cp16(_sb + soff[p],              pAh + g);                    \
            cp16(_sb + REGION + soff[p],     pAl + g);                    \
            cp16(_sb + 2 * REGION + soff[p], pBh + g);                    \
            cp16(_sb + 3 * REGION + soff[p], pBl + g);                    \
        }                                                                 \
        CP_COMMIT();                                                      \
    } while (0)

    float acc[4][4][4];
    #pragma unroll
    for (int mi = 0; mi < 4; mi++)
        #pragma unroll
        for (int ni = 0; ni < 4; ni++)
            #pragma unroll
            for (int q = 0; q < 4; q++)
                acc[mi][ni][q] = 0.0f;

    const int nk = K >> 6;   // chunks of 64 bf16

    // ---- prologue: stages 0..NSTAGE-2 ----
    LOAD_STAGE(0, 0);
    LOAD_STAGE(1, 64);

    const int arow = lane & 15;
    const int acol = lane & 16;   // byte offset within fragment pair

    int bufc = 0;           // buffer holding chunk c
    int bufn = NSTAGE - 1;  // buffer to fill next

    for (int c = 0; c < nk; c++) {
        if (c + 1 < nk) { CP_WAIT(1); } else { CP_WAIT(0); }
        __syncthreads();

        if (c + NSTAGE - 1 < nk)
            LOAD_STAGE(bufn, (c + NSTAGE - 1) * 64);

        const uint32_t sa = sbase + bufc * STAGE_BYTES;
        #pragma unroll
        for (int ks = 0; ks < 4; ks++) {
            const int col = ks * 32 + acol;
            uint32_t rah[4][4], ral[4][4], rbh[2][4], rbl[2][4];
            #pragma unroll
            for (int mi = 0; mi < 4; mi++) {
                const uint32_t ro = SWZ((wm + mi * 16 + arow) * 128 + col);
                ldsm_x4(rah[mi], sa + ro);
                ldsm_x4(ral[mi], sa + REGION + ro);
            }
            #pragma unroll
            for (int ng = 0; ng < 2; ng++) {
                const uint32_t ro = SWZ((wn + ng * 16 + arow) * 128 + col);
                ldsm_x4(rbh[ng], sa + 2 * REGION + ro);
                ldsm_x4(rbl[ng], sa + 3 * REGION + ro);
            }
            #pragma unroll
            for (int mi = 0; mi < 4; mi++)
                #pragma unroll
                for (int ni = 0; ni < 4; ni++) {
                    const uint32_t bh0 = rbh[ni >> 1][ni & 1];
                    const uint32_t bh1 = rbh[ni >> 1][2 + (ni & 1)];
                    mma16816(acc[mi][ni], rah[mi], bh0, bh1);
                    mma16816(acc[mi][ni], rah[mi],
                             rbl[ni >> 1][ni & 1], rbl[ni >> 1][2 + (ni & 1)]);
                    mma16816(acc[mi][ni], ral[mi], bh0, bh1);
                }
        }

        bufc = (bufc == NSTAGE - 1) ? 0 : bufc + 1;
        bufn = (bufn == NSTAGE - 1) ? 0 : bufn + 1;
    }
#undef LOAD_STAGE

    // ---- epilogue ----
    const int g = lane >> 2;
    const int t = lane & 3;
    #pragma unroll
    for (int mi = 0; mi < 4; mi++) {
        #pragma unroll
        for (int half = 0; half < 2; half++) {
            const int row = bm + wm + mi * 16 + g + half * 8;
            float br = 0.0f;
            if (BIAS == 2) br = bias[row];
            #pragma unroll
            for (int ni = 0; ni < 4; ni++) {
                const int colr = wn + ni * 8 + t * 2;
                float vx = acc[mi][ni][half * 2 + 0] * alpha;
                float vy = acc[mi][ni][half * 2 + 1] * alpha;
                if (BIAS == 1) {
                    vx += bias[bn + colr];
                    vy += bias[bn + colr + 1];
                } else if (BIAS == 2) {
                    vx += br; vy += br;
                }
                const size_t o = zC + (size_t)row * N + bn + colr;
                if (OUT_SPLIT) {
                    bf16 hx, hy, lx, ly;
                    split2(vx, vy, hx, hy, lx, ly);
                    __nv_bfloat162 h2; h2.x = hx; h2.y = hy;
                    __nv_bfloat162 l2; l2.x = lx; l2.y = ly;
                    *reinterpret_cast<__nv_bfloat162*>(Chi + o) = h2;
                    *reinterpret_cast<__nv_bfloat162*>(Clo + o) = l2;
                } else {
                    float2 v; v.x = vx; v.y = vy;
                    *reinterpret_cast<float2*>(C + o) = v;
                }
            }
        }
    }
}

// ---------------- X split: fp32 -> bf16 hi/lo ----------------
__global__ __launch_bounds__(256) void split_x(
    const float* __restrict__ in, bf16* __restrict__ hi, bf16* __restrict__ lo,
    size_t n4)
{
    const size_t i = (size_t)blockIdx.x * 256 + threadIdx.x;
    if (i >= n4) return;
    float4 v = reinterpret_cast<const float4*>(in)[i];
    bf16 hx, hy, hz, hw, lx, ly, lz, lw;
    split2(v.x, v.y, hx, hy, lx, ly);
    split2(v.z, v.w, hz, hw, lz, lw);
    __nv_bfloat162 h0, h1, l0, l1;
    h0.x = hx; h0.y = hy; h1.x = hz; h1.y = hw;
    l0.x = lx; l0.y = ly; l1.x = lz; l1.y = lw;
    uint2 ho, loo;
    ho.x  = *reinterpret_cast<uint32_t*>(&h0);
    ho.y  = *reinterpret_cast<uint32_t*>(&h1);
    loo.x = *reinterpret_cast<uint32_t*>(&l0);
    loo.y = *reinterpret_cast<uint32_t*>(&l1);
    reinterpret_cast<uint2*>(hi)[i] = ho;
    reinterpret_cast<uint2*>(lo)[i] = loo;
}

// ---------------- W transpose + split (1024x1024) ----------------
__global__ __launch_bounds__(256) void transpose_split(
    const float* __restrict__ in, bf16* __restrict__ hi, bf16* __restrict__ lo)
{
    __shared__ float t[32][33];
    const int tx = threadIdx.x, ty = threadIdx.y;
    const int x = blockIdx.x * 32 + tx;
    const int y0 = blockIdx.y * 32;
    #pragma unroll
    for (int i = ty; i < 32; i += 8)
        t[i][tx] = in[(size_t)(y0 + i) * DD + x];
    __syncthreads();
    const int xo = blockIdx.y * 32 + tx;
    const int yo = blockIdx.x * 32;
    #pragma unroll
    for (int i = ty; i < 32; i += 8) {
        float v = t[tx][i];
        bf16 h = __float2bfloat16(v);
        bf16 l = __float2bfloat16(v - __bfloat162float(h));
        hi[(size_t)(yo + i) * DD + xo] = h;
        lo[(size_t)(yo + i) * DD + xo] = l;
    }
}

// ---------------- softmax (fp32 in, bf16 hi/lo out) ----------------
__global__ __launch_bounds__(256) void softmax_split(
    const float* __restrict__ s, bf16* __restrict__ ph, bf16* __restrict__ pl)
{
    __shared__ float red[256];
    const size_t base = (size_t)blockIdx.x * SS;
    const float* row = s + base;
    const int tid = threadIdx.x;

    float m = -3.4e38f;
    #pragma unroll 2
    for (int i = tid; i < SS; i += 256) m = fmaxf(m, row[i]);
    red[tid] = m;
    __syncthreads();
    #pragma unroll
    for (int o = 128; o > 0; o >>= 1) {
        if (tid < o) red[tid] = fmaxf(red[tid], red[tid + o]);
        __syncthreads();
    }
    m = red[0];
    __syncthreads();

    float sum = 0.0f;
    float e[8];
    #pragma unroll
    for (int j = 0; j < 8; j++) {
        e[j] = __expf(row[tid + j * 256] - m);
        sum += e[j];
    }
    red[tid] = sum;
    __syncthreads();
    #pragma unroll
    for (int o = 128; o > 0; o >>= 1) {
        if (tid < o) red[tid] += red[tid + o];
        __syncthreads();
    }
    const float inv = 1.0f / red[0];

    #pragma unroll
    for (int j = 0; j < 8; j++) {
        float p = e[j] * inv;
        bf16 h = __float2bfloat16(p);
        bf16 l = __float2bfloat16(p - __bfloat162float(h));
        ph[base + tid + j * 256] = h;
        pl[base + tid + j * 256] = l;
    }
}

// ============================ launch ============================
extern "C" void kernel_launch(void* const* d_in, const int* in_sizes, int n_in,
                              void* d_out, int out_size)
{
    const float* x  = (const float*)d_in[0];
    const float* Wk = (const float*)d_in[1];
    const float* bk = (const float*)d_in[2];
    const float* Wq = (const float*)d_in[3];
    const float* bq = (const float*)d_in[4];
    const float* Wv = (const float*)d_in[5];
    const float* bv = (const float*)d_in[6];
    float* out = (float*)d_out;

    bf16 *xh, *xl, *wth, *wtl, *qh, *ql, *kh, *kl, *vth, *vtl, *ph, *pl;
    float* sp;
    cudaGetSymbolAddress((void**)&xh,  g_xh);
    cudaGetSymbolAddress((void**)&xl,  g_xl);
    cudaGetSymbolAddress((void**)&wth, g_wth);
    cudaGetSymbolAddress((void**)&wtl, g_wtl);
    cudaGetSymbolAddress((void**)&qh,  g_qh);
    cudaGetSymbolAddress((void**)&ql,  g_ql);
    cudaGetSymbolAddress((void**)&kh,  g_kh);
    cudaGetSymbolAddress((void**)&kl,  g_kl);
    cudaGetSymbolAddress((void**)&vth, g_vth);
    cudaGetSymbolAddress((void**)&vtl, g_vtl);
    cudaGetSymbolAddress((void**)&sp,  g_s);
    cudaGetSymbolAddress((void**)&ph,  g_ph);
    cudaGetSymbolAddress((void**)&pl,  g_pl);

    const size_t WW = (size_t)DD * DD;
    bf16* wkth = wth;        bf16* wktl = wtl;
    bf16* wqth = wth + WW;   bf16* wqtl = wtl + WW;
    bf16* wvth = wth + 2*WW; bf16* wvtl = wtl + 2*WW;

    cudaFuncSetAttribute(mma_gemm<0, 0>,
        cudaFuncAttributeMaxDynamicSharedMemorySize, GEMM_SMEM);
    cudaFuncSetAttribute(mma_gemm<1, 1>,
        cudaFuncAttributeMaxDynamicSharedMemorySize, GEMM_SMEM);
    cudaFuncSetAttribute(mma_gemm<1, 2>,
        cudaFuncAttributeMaxDynamicSharedMemorySize, GEMM_SMEM);

    const int M = BB * SS;  // 8192

    // Pre-split inputs
    {
        const size_t n4 = (size_t)M * DD / 4;
        split_x<<<(unsigned)((n4 + 255) / 256), 256>>>(x, xh, xl, n4);
        dim3 tb(32, 8), tg(32, 32);
        transpose_split<<<tg, tb>>>(Wk, wkth, wktl);
        transpose_split<<<tg, tb>>>(Wq, wqth, wqtl);
        transpose_split<<<tg, tb>>>(Wv, wvth, wvtl);
    }

    dim3 blk(256);

    // Q = X*Wq + bq ; K = X*Wk + bk  (split bf16 outputs, column bias)
    {
        dim3 grid(DD / 128, M / 128, 1);
        mma_gemm<1, 1><<<grid, blk, GEMM_SMEM>>>(
            xh, xl, wqth, wqtl, bq, nullptr, qh, ql,
            M, DD, DD, 1.0f, 0, 0, 0);
        mma_gemm<1, 1><<<grid, blk, GEMM_SMEM>>>(
            xh, xl, wkth, wktl, bk, nullptr, kh, kl,
            M, DD, DD, 1.0f, 0, 0, 0);
    }

    // V^T per batch: Vt[d][s] = sum_k Wv[k][d]*X[s][k] + bv[d] (row bias)
    {
        dim3 grid(SS / 128, DD / 128, BB);
        mma_gemm<1, 2><<<grid, blk, GEMM_SMEM>>>(
            wvth, wvtl, xh, xl, bv, nullptr, vth, vtl,
            DD, SS, DD, 1.0f, 0, (long)SS * DD, (long)DD * SS);
    }

    // Scores: S_b = Q_b * K_b^T / 32  (fp32 out)
    {
        dim3 grid(SS / 128, SS / 128, BB);
        mma_gemm<0, 0><<<grid, blk, GEMM_SMEM>>>(
            qh, ql, kh, kl, nullptr, sp, nullptr, nullptr,
            SS, SS, DD, 1.0f / 32.0f,
            (long)SS * DD, (long)SS * DD, (long)SS * SS);
    }

    // Softmax over keys -> split probs
    softmax_split<<<BB * SS, 256>>>(sp, ph, pl);

    // Out: O_b = P_b * V_b  (fp32 out)
    {
        dim3 grid(DD / 128, SS / 128, BB);
        mma_gemm<0, 0><<<grid, blk, GEMM_SMEM>>>(
            ph, pl, vth, vtl, nullptr, out, nullptr, nullptr,
            SS, DD, SS, 1.0f,
            (long)SS * SS, (long)DD * SS, (long)SS * DD);
    }
}

// round 5
// speedup vs baseline: 2.7236x; 1.0125x over previous
#include <cuda_runtime.h>
#include <cuda_bf16.h>
#include <cstdint>
#include <cstddef>

// Problem constants (B=4, S=2048, D=1024)
#define BB 4
#define SS 2048
#define DD 1024

typedef __nv_bfloat16 bf16;

// ---------------- scratch (__device__ globals, no-alloc rule) ----------------
__device__ bf16  g_xh [(size_t)BB * SS * DD];   // X hi/lo  [B*S, D]
__device__ bf16  g_xl [(size_t)BB * SS * DD];
__device__ bf16  g_wth[3][(size_t)DD * DD];     // W^T hi/lo (k,q,v)
__device__ bf16  g_wtl[3][(size_t)DD * DD];
__device__ bf16  g_qh [(size_t)BB * SS * DD];   // Q hi/lo
__device__ bf16  g_ql [(size_t)BB * SS * DD];
__device__ bf16  g_kh [(size_t)BB * SS * DD];   // K hi/lo
__device__ bf16  g_kl [(size_t)BB * SS * DD];
__device__ bf16  g_vth[(size_t)BB * DD * SS];   // V^T hi/lo [D, S] per batch
__device__ bf16  g_vtl[(size_t)BB * DD * SS];
__device__ float g_s  [(size_t)BB * SS * SS];   // scores (fp32, softmax input)
__device__ bf16  g_ph [(size_t)BB * SS * SS];   // probs hi/lo
__device__ bf16  g_pl [(size_t)BB * SS * SS];

// ---------------- helpers ----------------
__device__ __forceinline__ uint32_t smem_u32(const void* p) {
    uint32_t a;
    asm("{ .reg .u64 t; cvta.to.shared.u64 t, %1; cvt.u32.u64 %0, t; }"
        : "=r"(a) : "l"(p));
    return a;
}

// 128B-row XOR swizzle: byte bits [6:4] ^= bits [9:7]
#define SWZ(off) ((uint32_t)(off) ^ ((((uint32_t)(off)) >> 3) & 0x70u))

__device__ __forceinline__ void cp16(uint32_t dst, const void* src) {
    asm volatile("cp.async.cg.shared.global [%0], [%1], 16;"
                 :: "r"(dst), "l"(src) : "memory");
}
#define CP_COMMIT() asm volatile("cp.async.commit_group;" ::: "memory")
#define CP_WAIT(n)  asm volatile("cp.async.wait_group %0;" :: "n"(n) : "memory")

__device__ __forceinline__ void ldsm_x4(uint32_t* r, uint32_t addr) {
    asm volatile("ldmatrix.sync.aligned.m8n8.x4.shared.b16 {%0,%1,%2,%3}, [%4];"
                 : "=r"(r[0]), "=r"(r[1]), "=r"(r[2]), "=r"(r[3]) : "r"(addr));
}

__device__ __forceinline__ void mma16816(float* c, const uint32_t* a,
                                         uint32_t b0, uint32_t b1) {
    asm volatile(
        "mma.sync.aligned.m16n8k16.row.col.f32.bf16.bf16.f32 "
        "{%0,%1,%2,%3}, {%4,%5,%6,%7}, {%8,%9}, {%0,%1,%2,%3};"
        : "+f"(c[0]), "+f"(c[1]), "+f"(c[2]), "+f"(c[3])
        : "r"(a[0]), "r"(a[1]), "r"(a[2]), "r"(a[3]), "r"(b0), "r"(b1));
}

__device__ __forceinline__ void split2(float x, float y, bf16& hx, bf16& hy,
                                       bf16& lx, bf16& ly) {
    hx = __float2bfloat16(x);
    hy = __float2bfloat16(y);
    lx = __float2bfloat16(x - __bfloat162float(hx));
    ly = __float2bfloat16(y - __bfloat162float(hy));
}

// ============================ GEMM kernel ============================
// D = alpha * A[M,K] * B[N,K]^T (+bias); A,B pre-split bf16 hi/lo, K-major.
// Block 128x256, 8 warps (2x4 grid of 64x64 warp tiles), K chunk = 64 bf16.
// Stage: Ah(16K)|Al(16K)|Bh(32K)|Bl(32K) = 96KB; 2 stages = 192KB smem.
#define OFF_AL 16384
#define OFF_BH 32768
#define OFF_BL 65536
#define STAGE_BYTES 98304
#define GEMM_SMEM (2 * STAGE_BYTES)

// BIAS: 0 none, 1 column (bias[col]), 2 row (bias[row])
template<int OUT_SPLIT, int BIAS>
__global__ __launch_bounds__(256, 1) void mma_gemm(
    const bf16* __restrict__ Ahi, const bf16* __restrict__ Alo,
    const bf16* __restrict__ Bhi, const bf16* __restrict__ Blo,
    const float* __restrict__ bias,
    float* __restrict__ C, bf16* __restrict__ Chi, bf16* __restrict__ Clo,
    int M, int N, int K, float alpha,
    long sA, long sB, long sC)
{
    extern __shared__ __align__(1024) char smem[];
    const uint32_t sbase = smem_u32(smem);

    const size_t zA = (size_t)blockIdx.z * sA;
    const size_t zB = (size_t)blockIdx.z * sB;
    const size_t zC = (size_t)blockIdx.z * sC;

    const int tid  = threadIdx.x;
    const int w    = tid >> 5;
    const int lane = tid & 31;
    const int bm = blockIdx.y * 128;
    const int bn = blockIdx.x * 256;
    const int wm = (w & 1) * 64;      // 2 warp rows
    const int wn = (w >> 1) * 64;     // 4 warp cols x 64

    // ---- cp.async mapping: ldr row 0..31, ldc 16B chunk 0..7 ----
    const int ldr = tid >> 3;
    const int ldc = tid & 7;
    const bf16* pAh = Ahi + zA + (size_t)(bm + ldr) * K + ldc * 8;
    const bf16* pAl = Alo + zA + (size_t)(bm + ldr) * K + ldc * 8;
    const bf16* pBh = Bhi + zB + (size_t)(bn + ldr) * K + ldc * 8;
    const bf16* pBl = Blo + zB + (size_t)(bn + ldr) * K + ldc * 8;
    uint32_t soff[8];
    size_t rK[8];
    #pragma unroll
    for (int p = 0; p < 8; p++) {
        soff[p] = SWZ((ldr + p * 32) * 128 + ldc * 16);
        rK[p] = (size_t)(p * 32) * K;
    }

#define LOAD_STAGE(sbuf, k0) do {                                         \
        const uint32_t _sb = sbase + (sbuf) * STAGE_BYTES;                \
        _Pragma("unroll")                                                 \
        for (int p = 0; p < 4; p++) {                                     \
            const size_t g = rK[p] + (size_t)(k0);                        \
            cp16(_sb + soff[p],          pAh + g);                        \
            cp16(_sb + OFF_AL + soff[p], pAl + g);                        \
        }                                                                 \
        _Pragma("unroll")                                                 \
        for (int p = 0; p < 8; p++) {                                     \
            const size_t g = rK[p] + (size_t)(k0);                        \
            cp16(_sb + OFF_BH + soff[p], pBh + g);                        \
            cp16(_sb + OFF_BL + soff[p], pBl + g);                        \
        }                                                                 \
        CP_COMMIT();                                                      \
    } while (0)

    float acc[4][8][4];
    #pragma unroll
    for (int mi = 0; mi < 4; mi++)
        #pragma unroll
        for (int ni = 0; ni < 8; ni++)
            #pragma unroll
            for (int q = 0; q < 4; q++)
                acc[mi][ni][q] = 0.0f;

    const int nk = K >> 6;   // chunks of 64 bf16

    LOAD_STAGE(0, 0);

    const int arow = lane & 15;
    const int acol = lane & 16;

    for (int c = 0; c < nk; c++) {
        if (c + 1 < nk) {
            LOAD_STAGE((c + 1) & 1, (c + 1) * 64);
            CP_WAIT(1);
        } else {
            CP_WAIT(0);
        }
        __syncthreads();

        const uint32_t sa = sbase + (c & 1) * STAGE_BYTES;
        #pragma unroll
        for (int ks = 0; ks < 4; ks++) {
            const int col = ks * 32 + acol;
            uint32_t rbh[4][4], rbl[4][4];
            #pragma unroll
            for (int ng = 0; ng < 4; ng++) {
                const uint32_t ro = SWZ((wn + ng * 16 + arow) * 128 + col);
                ldsm_x4(rbh[ng], sa + OFF_BH + ro);
                ldsm_x4(rbl[ng], sa + OFF_BL + ro);
            }
            #pragma unroll
            for (int mi = 0; mi < 4; mi++) {
                const uint32_t ro = SWZ((wm + mi * 16 + arow) * 128 + col);
                uint32_t rah[4], ral[4];
                ldsm_x4(rah, sa + ro);
                ldsm_x4(ral, sa + OFF_AL + ro);
                #pragma unroll
                for (int ni = 0; ni < 8; ni++) {
                    const uint32_t bh0 = rbh[ni >> 1][ni & 1];
                    const uint32_t bh1 = rbh[ni >> 1][2 + (ni & 1)];
                    mma16816(acc[mi][ni], rah, bh0, bh1);
                    mma16816(acc[mi][ni], rah,
                             rbl[ni >> 1][ni & 1], rbl[ni >> 1][2 + (ni & 1)]);
                    mma16816(acc[mi][ni], ral, bh0, bh1);
                }
            }
        }
        __syncthreads();
    }
#undef LOAD_STAGE

    // ---- epilogue ----
    const int g = lane >> 2;
    const int t = lane & 3;
    #pragma unroll
    for (int mi = 0; mi < 4; mi++) {
        #pragma unroll
        for (int half = 0; half < 2; half++) {
            const int row = bm + wm + mi * 16 + g + half * 8;
            float br = 0.0f;
            if (BIAS == 2) br = bias[row];
            #pragma unroll
            for (int ni = 0; ni < 8; ni++) {
                const int colr = wn + ni * 8 + t * 2;
                float vx = acc[mi][ni][half * 2 + 0] * alpha;
                float vy = acc[mi][ni][half * 2 + 1] * alpha;
                if (BIAS == 1) {
                    vx += bias[bn + colr];
                    vy += bias[bn + colr + 1];
                } else if (BIAS == 2) {
                    vx += br; vy += br;
                }
                const size_t o = zC + (size_t)row * N + bn + colr;
                if (OUT_SPLIT) {
                    bf16 hx, hy, lx, ly;
                    split2(vx, vy, hx, hy, lx, ly);
                    __nv_bfloat162 h2; h2.x = hx; h2.y = hy;
                    __nv_bfloat162 l2; l2.x = lx; l2.y = ly;
                    *reinterpret_cast<__nv_bfloat162*>(Chi + o) = h2;
                    *reinterpret_cast<__nv_bfloat162*>(Clo + o) = l2;
                } else {
                    float2 v; v.x = vx; v.y = vy;
                    *reinterpret_cast<float2*>(C + o) = v;
                }
            }
        }
    }
}

// ---------------- X split: fp32 -> bf16 hi/lo ----------------
__global__ __launch_bounds__(256) void split_x(
    const float* __restrict__ in, bf16* __restrict__ hi, bf16* __restrict__ lo,
    size_t n4)
{
    const size_t i = (size_t)blockIdx.x * 256 + threadIdx.x;
    if (i >= n4) return;
    float4 v = reinterpret_cast<const float4*>(in)[i];
    bf16 hx, hy, hz, hw, lx, ly, lz, lw;
    split2(v.x, v.y, hx, hy, lx, ly);
    split2(v.z, v.w, hz, hw, lz, lw);
    __nv_bfloat162 h0, h1, l0, l1;
    h0.x = hx; h0.y = hy; h1.x = hz; h1.y = hw;
    l0.x = lx; l0.y = ly; l1.x = lz; l1.y = lw;
    uint2 ho, loo;
    ho.x  = *reinterpret_cast<uint32_t*>(&h0);
    ho.y  = *reinterpret_cast<uint32_t*>(&h1);
    loo.x = *reinterpret_cast<uint32_t*>(&l0);
    loo.y = *reinterpret_cast<uint32_t*>(&l1);
    reinterpret_cast<uint2*>(hi)[i] = ho;
    reinterpret_cast<uint2*>(lo)[i] = loo;
}

// ---------------- W transpose + split (1024x1024) ----------------
__global__ __launch_bounds__(256) void transpose_split(
    const float* __restrict__ in, bf16* __restrict__ hi, bf16* __restrict__ lo)
{
    __shared__ float t[32][33];
    const int tx = threadIdx.x, ty = threadIdx.y;
    const int x = blockIdx.x * 32 + tx;
    const int y0 = blockIdx.y * 32;
    #pragma unroll
    for (int i = ty; i < 32; i += 8)
        t[i][tx] = in[(size_t)(y0 + i) * DD + x];
    __syncthreads();
    const int xo = blockIdx.y * 32 + tx;
    const int yo = blockIdx.x * 32;
    #pragma unroll
    for (int i = ty; i < 32; i += 8) {
        float v = t[tx][i];
        bf16 h = __float2bfloat16(v);
        bf16 l = __float2bfloat16(v - __bfloat162float(h));
        hi[(size_t)(yo + i) * DD + xo] = h;
        lo[(size_t)(yo + i) * DD + xo] = l;
    }
}

// ---------------- softmax (fp32 in, bf16 hi/lo out) ----------------
__global__ __launch_bounds__(256) void softmax_split(
    const float* __restrict__ s, bf16* __restrict__ ph, bf16* __restrict__ pl)
{
    __shared__ float red[256];
    const size_t base = (size_t)blockIdx.x * SS;
    const float* row = s + base;
    const int tid = threadIdx.x;

    float m = -3.4e38f;
    #pragma unroll 2
    for (int i = tid; i < SS; i += 256) m = fmaxf(m, row[i]);
    red[tid] = m;
    __syncthreads();
    #pragma unroll
    for (int o = 128; o > 0; o >>= 1) {
        if (tid < o) red[tid] = fmaxf(red[tid], red[tid + o]);
        __syncthreads();
    }
    m = red[0];
    __syncthreads();

    float sum = 0.0f;
    float e[8];
    #pragma unroll
    for (int j = 0; j < 8; j++) {
        e[j] = __expf(row[tid + j * 256] - m);
        sum += e[j];
    }
    red[tid] = sum;
    __syncthreads();
    #pragma unroll
    for (int o = 128; o > 0; o >>= 1) {
        if (tid < o) red[tid] += red[tid + o];
        __syncthreads();
    }
    const float inv = 1.0f / red[0];

    #pragma unroll
    for (int j = 0; j < 8; j++) {
        float p = e[j] * inv;
        bf16 h = __float2bfloat16(p);
        bf16 l = __float2bfloat16(p - __bfloat162float(h));
        ph[base + tid + j * 256] = h;
        pl[base + tid + j * 256] = l;
    }
}

// ============================ launch ============================
extern "C" void kernel_launch(void* const* d_in, const int* in_sizes, int n_in,
                              void* d_out, int out_size)
{
    const float* x  = (const float*)d_in[0];
    const float* Wk = (const float*)d_in[1];
    const float* bk = (const float*)d_in[2];
    const float* Wq = (const float*)d_in[3];
    const float* bq = (const float*)d_in[4];
    const float* Wv = (const float*)d_in[5];
    const float* bv = (const float*)d_in[6];
    float* out = (float*)d_out;

    bf16 *xh, *xl, *wth, *wtl, *qh, *ql, *kh, *kl, *vth, *vtl, *ph, *pl;
    float* sp;
    cudaGetSymbolAddress((void**)&xh,  g_xh);
    cudaGetSymbolAddress((void**)&xl,  g_xl);
    cudaGetSymbolAddress((void**)&wth, g_wth);
    cudaGetSymbolAddress((void**)&wtl, g_wtl);
    cudaGetSymbolAddress((void**)&qh,  g_qh);
    cudaGetSymbolAddress((void**)&ql,  g_ql);
    cudaGetSymbolAddress((void**)&kh,  g_kh);
    cudaGetSymbolAddress((void**)&kl,  g_kl);
    cudaGetSymbolAddress((void**)&vth, g_vth);
    cudaGetSymbolAddress((void**)&vtl, g_vtl);
    cudaGetSymbolAddress((void**)&sp,  g_s);
    cudaGetSymbolAddress((void**)&ph,  g_ph);
    cudaGetSymbolAddress((void**)&pl,  g_pl);

    const size_t WW = (size_t)DD * DD;
    bf16* wkth = wth;        bf16* wktl = wtl;
    bf16* wqth = wth + WW;   bf16* wqtl = wtl + WW;
    bf16* wvth = wth + 2*WW; bf16* wvtl = wtl + 2*WW;

    cudaFuncSetAttribute(mma_gemm<0, 0>,
        cudaFuncAttributeMaxDynamicSharedMemorySize, GEMM_SMEM);
    cudaFuncSetAttribute(mma_gemm<1, 1>,
        cudaFuncAttributeMaxDynamicSharedMemorySize, GEMM_SMEM);
    cudaFuncSetAttribute(mma_gemm<1, 2>,
        cudaFuncAttributeMaxDynamicSharedMemorySize, GEMM_SMEM);

    const int M = BB * SS;  // 8192

    // Pre-split inputs
    {
        const size_t n4 = (size_t)M * DD / 4;
        split_x<<<(unsigned)((n4 + 255) / 256), 256>>>(x, xh, xl, n4);
        dim3 tb(32, 8), tg(32, 32);
        transpose_split<<<tg, tb>>>(Wk, wkth, wktl);
        transpose_split<<<tg, tb>>>(Wq, wqth, wqtl);
        transpose_split<<<tg, tb>>>(Wv, wvth, wvtl);
    }

    dim3 blk(256);

    // Q = X*Wq + bq ; K = X*Wk + bk  (split bf16 outputs, column bias)
    {
        dim3 grid(DD / 256, M / 128, 1);
        mma_gemm<1, 1><<<grid, blk, GEMM_SMEM>>>(
            xh, xl, wqth, wqtl, bq, nullptr, qh, ql,
            M, DD, DD, 1.0f, 0, 0, 0);
        mma_gemm<1, 1><<<grid, blk, GEMM_SMEM>>>(
            xh, xl, wkth, wktl, bk, nullptr, kh, kl,
            M, DD, DD, 1.0f, 0, 0, 0);
    }

    // V^T per batch: Vt[d][s] = sum_k Wv[k][d]*X[s][k] + bv[d] (row bias)
    {
        dim3 grid(SS / 256, DD / 128, BB);
        mma_gemm<1, 2><<<grid, blk, GEMM_SMEM>>>(
            wvth, wvtl, xh, xl, bv, nullptr, vth, vtl,
            DD, SS, DD, 1.0f, 0, (long)SS * DD, (long)DD * SS);
    }

    // Scores: S_b = Q_b * K_b^T / 32  (fp32 out)
    {
        dim3 grid(SS / 256, SS / 128, BB);
        mma_gemm<0, 0><<<grid, blk, GEMM_SMEM>>>(
            qh, ql, kh, kl, nullptr, sp, nullptr, nullptr,
            SS, SS, DD, 1.0f / 32.0f,
            (long)SS * DD, (long)SS * DD, (long)SS * SS);
    }

    // Softmax over keys -> split probs
    softmax_split<<<BB * SS, 256>>>(sp, ph, pl);

    // Out: O_b = P_b * V_b  (fp32 out)
    {
        dim3 grid(DD / 256, SS / 128, BB);
        mma_gemm<0, 0><<<grid, blk, GEMM_SMEM>>>(
            ph, pl, vth, vtl, nullptr, out, nullptr, nullptr,
            SS, DD, SS, 1.0f,
            (long)SS * SS, (long)DD * SS, (long)SS * DD);
    }
}